// round 15
// baseline (speedup 1.0000x reference)
#include <cuda_runtime.h>
#include <cuda_fp16.h>
#include <math.h>
#include <cstdint>

// Problem constants
#define B_  4
#define N_  2048
#define E_  512
#define H_  8
#define D_  64
#define BH_ 32   // B_*H_

// ---------------- scratch (static __device__; no allocations allowed) -------
// "p16" = within-16-group interleave: pos 4j..4j+3 <- cols (2j,2j+1,2j+8,2j+9)
__device__ __half g_xh [B_ * N_ * E_];    // x, fp16, e p16-permuted
__device__ __half g_Wkh[E_ * E_];         // Wk, fp16, e p16-permuted
__device__ __half g_Wvh[E_ * E_];         // Wv, fp16, e p16-permuted
__device__ __half g_Kh [BH_ * N_ * D_];   // K [bh][n][d p16-permuted] fp16
__device__ __half g_Vh [BH_ * N_ * D_];   // V [bh][n][d] natural fp16
__device__ __half g_VTh[BH_ * D_ * N_];   // V^T [bh][d][n] fp16

// ---------------- helpers (sm_80-era PTX only) --------------------------------
__device__ __forceinline__ void mma_f16(float* d, const uint32_t* a,
                                        uint32_t b0, uint32_t b1) {
    asm volatile(
        "mma.sync.aligned.m16n8k16.row.col.f32.f16.f16.f32 "
        "{%0,%1,%2,%3}, {%4,%5,%6,%7}, {%8,%9}, {%0,%1,%2,%3};\n"
        : "+f"(d[0]), "+f"(d[1]), "+f"(d[2]), "+f"(d[3])
        : "r"(a[0]), "r"(a[1]), "r"(a[2]), "r"(a[3]), "r"(b0), "r"(b1));
}
__device__ __forceinline__ uint32_t pack2(float x, float y) {
    __half2 h = __floats2half2_rn(x, y);
    return *(uint32_t*)&h;
}
__device__ __forceinline__ uint32_t smem_u32(const void* p) {
    uint32_t a;
    asm("{ .reg .u64 t; cvta.to.shared.u64 t, %1; cvt.u32.u64 %0, t; }"
        : "=r"(a) : "l"(p));
    return a;
}
#define CP16(dst, src) \
    asm volatile("cp.async.cg.shared.global [%0], [%1], 16;" :: "r"(dst), "l"(src) : "memory")
#define CP_COMMIT() asm volatile("cp.async.commit_group;" ::: "memory")
#define CP_WAIT(n)  asm volatile("cp.async.wait_group %0;" :: "n"(n) : "memory")

// ---------------- fp32 -> fp16 + p16 permutation ------------------------------
// out[16G + 4j + {0,1,2,3}] = in[16G + {2j, 2j+1, 2j+8, 2j+9}]
__global__ void round_perm16(const float* __restrict__ src,
                             __half* __restrict__ dst, int nq) {
    int i = blockIdx.x * 256 + threadIdx.x;
    if (i >= nq) return;
    int G = i >> 2, j = i & 3;
    int base = 16 * G + 2 * j;
    float2 a = *(const float2*)(src + base);      // cols 2j, 2j+1
    float2 b = *(const float2*)(src + base + 8);  // cols 2j+8, 2j+9
    uint2 o = make_uint2(pack2(a.x, a.y), pack2(b.x, b.y));
    *(uint2*)(dst + 4 * i) = o;
}

// ---------------- K/V projection GEMM (fp16 mma, cp.async 2-stage) -----------
// Tile 128m x 64c, z: 0=K, 1=V. 16 e-chunks of 32 (2 ksteps of k16).
// Stride 80 halfs (== 16 mod 64): paired LDS.64 fragments conflict-free.
#define PJ_STRH 80
#define PJ_WOFH (128 * PJ_STRH)              // 10240 halfs
#define PJ_BUFH (192 * PJ_STRH)              // 15360 halfs per stage
#define PJ_SMEM (2 * PJ_BUFH * 2)            // 61440 B

__device__ __forceinline__ void pj_issue(uint32_t sb, int stage, int k0,
                                         const __half* __restrict__ x,
                                         const __half* __restrict__ W,
                                         int m0, int c0, int tid) {
    uint32_t base = sb + stage * (PJ_BUFH * 2);
#pragma unroll
    for (int it = 0; it < 2; it++) {           // xs: 128 rows x 4 chunks = 512
        int i = it * 256 + tid;
        int r = i >> 2, c8 = (i & 3) * 8;
        CP16(base + (r * PJ_STRH + c8) * 2,
             x + (size_t)(m0 + r) * E_ + k0 + c8);
    }
    {                                          // ws: 64 rows x 4 chunks = 256
        int i = tid;
        int r = i >> 2, c8 = (i & 3) * 8;
        CP16(base + (PJ_WOFH + r * PJ_STRH + c8) * 2,
             W + (size_t)(c0 + r) * E_ + k0 + c8);
    }
    CP_COMMIT();
}

__global__ void __launch_bounds__(256) proj_mma(const float* __restrict__ bk,
                                                const float* __restrict__ bv) {
    extern __shared__ __half smh[];
    uint32_t sb = smem_u32(smh);
    int tid = threadIdx.x;
    int w = tid >> 5, lane = tid & 31;
    int qq = lane & 3, g = lane >> 2;
    int m0 = blockIdx.x * 128;
    int h  = blockIdx.y;
    int c0 = h * 64;
    int z  = blockIdx.z;
    const __half* x    = g_xh;
    const __half* W    = z ? g_Wvh : g_Wkh;
    const float*  bias = z ? bv : bk;
    __half* dst        = z ? g_Vh : g_Kh;

    float acc[8][4];
#pragma unroll
    for (int i = 0; i < 8; i++)
#pragma unroll
        for (int j = 0; j < 4; j++) acc[i][j] = 0.f;

    pj_issue(sb, 0, 0, x, W, m0, c0, tid);

    for (int ec = 0; ec < 16; ec++) {
        if (ec < 15) pj_issue(sb, (ec + 1) & 1, (ec + 1) * 32, x, W, m0, c0, tid);
        if (ec < 15) { CP_WAIT(1); } else { CP_WAIT(0); }
        __syncthreads();

        const __half* bf = smh + (ec & 1) * PJ_BUFH;
        uint32_t af[2][4];
#pragma unroll
        for (int kk = 0; kk < 2; kk++) {       // paired A-frag loads (p16 e-dim)
            uint2 lo = *(const uint2*)&bf[(16 * w + g) * PJ_STRH + 16 * kk + 4 * qq];
            uint2 hi = *(const uint2*)&bf[(16 * w + g + 8) * PJ_STRH + 16 * kk + 4 * qq];
            af[kk][0] = lo.x; af[kk][2] = lo.y;
            af[kk][1] = hi.x; af[kk][3] = hi.y;
        }
#pragma unroll
        for (int nt = 0; nt < 8; nt++) {
#pragma unroll
            for (int kk = 0; kk < 2; kk++) {   // paired B-frag loads
                uint2 bb = *(const uint2*)&bf[PJ_WOFH + (8 * nt + g) * PJ_STRH + 16 * kk + 4 * qq];
                mma_f16(acc[nt], af[kk], bb.x, bb.y);
            }
        }
        __syncthreads();
    }

    // epilogue: bias add in fp32 (original col index), pack fp16
    int r0 = m0 + 16 * w + g;
    int b0i = r0 >> 11, n0i = r0 & 2047;
    int bh = b0i * 8 + h;
    __half* p0 = dst + ((size_t)bh * N_ + n0i) * D_;
    __half* p8 = p0 + 8 * D_;
#pragma unroll
    for (int nt = 0; nt < 8; nt++) {
        int c = 8 * nt + 2 * qq;               // original output col (local)
        float bb0 = bias[c0 + c], bb1 = bias[c0 + c + 1];
        // K gets d p16-permuted on store; V stays natural
        int cb = z ? c : (16 * (nt >> 1) + 4 * qq + 2 * (nt & 1));
        *(uint32_t*)&p0[cb] = pack2(acc[nt][0] + bb0, acc[nt][1] + bb1);
        *(uint32_t*)&p8[cb] = pack2(acc[nt][2] + bb0, acc[nt][3] + bb1);
    }
}

// ---------------- V transpose (fp16): [bh][n][d] -> [bh][d][n] ---------------
__global__ void __launch_bounds__(256) vtrans() {
    __shared__ __half t[64][65];
    int bh = blockIdx.y;
    int n0 = blockIdx.x * 64;
    int tid = threadIdx.x;
    const __half* src = g_Vh + ((size_t)bh * N_ + n0) * D_;
#pragma unroll
    for (int it = 0; it < 16; it++) {
        int i = it * 256 + tid;
        int r = i >> 6, c = i & 63;
        t[r][c] = src[(size_t)r * D_ + c];
    }
    __syncthreads();
    __half* dstb = g_VTh + (size_t)bh * D_ * N_ + n0;
#pragma unroll
    for (int it = 0; it < 16; it++) {
        int i = it * 256 + tid;
        int d = i >> 6, n = i & 63;
        dstb[(size_t)d * N_ + n] = t[n][d];
    }
}

// ---------------- fp16 mma flash attention (online max, deferred PV) ---------
// 4-buffer cp.async ring, ONE barrier/iter. Deferred PV extends the live set
// to {t+2 writing, t+1 loaded, t in S, t-1 in PV} -> ring-4 REQUIRED (ring-3
// raced: issue of t+2 hits buffer (t-1)%3 before slow warps finish PV(t-1)).
#define KS_STRH 80
#define VS_STRH 72
#define AT_VOFH (64 * KS_STRH)                // 5120 halfs
#define AT_BUFH (64 * KS_STRH + 64 * VS_STRH) // 9728 halfs per stage
#define ATTN_SMEM (4 * AT_BUFH * 2)           // 77824 B

__device__ __forceinline__ void at_issue(uint32_t sb, int stage, int k0,
                                         const __half* __restrict__ Kb,
                                         const __half* __restrict__ VTb, int tid) {
    uint32_t base = sb + stage * (AT_BUFH * 2);
#pragma unroll
    for (int it = 0; it < 2; it++) {          // K tile: 64 keys x 8 chunks = 512
        int i = it * 256 + tid;
        int r = i >> 3, c8 = (i & 7) * 8;
        CP16(base + (r * KS_STRH + c8) * 2,
             Kb + (size_t)(k0 + r) * D_ + c8);
    }
#pragma unroll
    for (int it = 0; it < 2; it++) {          // V^T tile: 64 d x 8 chunks = 512
        int i = it * 256 + tid;
        int r = i >> 3, c8 = (i & 7) * 8;
        CP16(base + (AT_VOFH + r * VS_STRH + c8) * 2,
             VTb + (size_t)r * N_ + k0 + c8);
    }
    CP_COMMIT();
}

__global__ void __launch_bounds__(256, 2) attn_mma(float* __restrict__ out) {
    extern __shared__ __half smh[];
    uint32_t sb = smem_u32(smh);

    int tid = threadIdx.x;
    int w = tid >> 5, lane = tid & 31;
    int qq = lane & 3, g = lane >> 2;
    int q0 = blockIdx.x * 128;
    int bh = blockIdx.y;
    int b = bh >> 3, h = bh & 7;

    const __half* Kb  = g_Kh  + (size_t)bh * N_ * D_;
    const __half* VTb = g_VTh + (size_t)bh * D_ * N_;

    // Q fragments: paired uint2 gmem loads (K stored d p16-permuted)
    int qrow = q0 + 16 * w + g;
    uint32_t qf[4][4];
#pragma unroll
    for (int dk = 0; dk < 4; dk++) {
        uint2 lo = *(const uint2*)&Kb[(size_t)qrow * D_ + 16 * dk + 4 * qq];
        uint2 hi = *(const uint2*)&Kb[(size_t)(qrow + 8) * D_ + 16 * dk + 4 * qq];
        qf[dk][0] = lo.x; qf[dk][2] = lo.y;
        qf[dk][1] = hi.x; qf[dk][3] = hi.y;
    }

    float oAcc[8][4];
#pragma unroll
    for (int i = 0; i < 8; i++)
#pragma unroll
        for (int j = 0; j < 4; j++) oAcc[i][j] = 0.f;
    float m0 = -1e30f, m8 = -1e30f, l0 = 0.f, l8 = 0.f;
    uint32_t pa[4][4];                         // deferred P fragments (tile t-1)

    at_issue(sb, 0, 0, Kb, VTb, tid);

    for (int t = 0; t < 32; t++) {
        if (t < 31) at_issue(sb, (t + 1) & 3, (t + 1) * 64, Kb, VTb, tid);
        if (t < 31) { CP_WAIT(1); } else { CP_WAIT(0); }
        __syncthreads();

        const __half* Ksb = smh + (t & 3) * AT_BUFH;

        // ---- S(t): all 64 keys, paired B-frag loads ----
        float s[4][8];
#pragma unroll
        for (int kk = 0; kk < 4; kk++) {
#pragma unroll
            for (int j = 0; j < 8; j++) s[kk][j] = 0.f;
            int rowE = (16 * kk + g) * KS_STRH;
            int rowO = (16 * kk + 8 + g) * KS_STRH;
#pragma unroll
            for (int dk = 0; dk < 4; dk++) {
                uint2 eb = *(const uint2*)&Ksb[rowE + 16 * dk + 4 * qq];
                mma_f16(&s[kk][0], qf[dk], eb.x, eb.y);
                uint2 ob = *(const uint2*)&Ksb[rowO + 16 * dk + 4 * qq];
                mma_f16(&s[kk][4], qf[dk], ob.x, ob.y);
            }
        }

        // ---- PV(t-1): overlaps softmax(t) below ----
        if (t > 0) {
            const __half* Vprev = smh + ((t + 3) & 3) * AT_BUFH + AT_VOFH;
#pragma unroll
            for (int kk = 0; kk < 4; kk++)
#pragma unroll
                for (int vt = 0; vt < 8; vt++) {
                    int vrow = (8 * vt + g) * VS_STRH;
                    uint32_t b0 = *(const uint32_t*)&Vprev[vrow + 16 * kk + 2 * qq];
                    uint32_t b1 = *(const uint32_t*)&Vprev[vrow + 16 * kk + 8 + 2 * qq];
                    mma_f16(oAcc[vt], pa[kk], b0, b1);
                }
        }

        // ---- online max (exact) ----
        float r0 = s[0][0], r8 = s[0][2];
#pragma unroll
        for (int kk = 0; kk < 4; kk++) {
            r0 = fmaxf(r0, fmaxf(fmaxf(s[kk][0], s[kk][1]), fmaxf(s[kk][4], s[kk][5])));
            r8 = fmaxf(r8, fmaxf(fmaxf(s[kk][2], s[kk][3]), fmaxf(s[kk][6], s[kk][7])));
        }
        r0 = fmaxf(r0, __shfl_xor_sync(0xffffffffu, r0, 1));
        r0 = fmaxf(r0, __shfl_xor_sync(0xffffffffu, r0, 2));
        r8 = fmaxf(r8, __shfl_xor_sync(0xffffffffu, r8, 1));
        r8 = fmaxf(r8, __shfl_xor_sync(0xffffffffu, r8, 2));
        float m0n = fmaxf(m0, r0), m8n = fmaxf(m8, r8);
        float al0 = __expf(m0 - m0n), al8 = __expf(m8 - m8n);
        m0 = m0n; m8 = m8n;
        l0 *= al0; l8 *= al8;
        if (al0 != 1.f || al8 != 1.f) {        // rescale only when max moved
#pragma unroll
            for (int vt = 0; vt < 8; vt++) {
                oAcc[vt][0] *= al0; oAcc[vt][1] *= al0;
                oAcc[vt][2] *= al8; oAcc[vt][3] *= al8;
            }
        }

        // ---- exp, accumulate l, pack P(t) for next-iter PV ----
#pragma unroll
        for (int kk = 0; kk < 4; kk++) {
            float pE0 = __expf(s[kk][0] - m0), pE1 = __expf(s[kk][1] - m0);
            float pE2 = __expf(s[kk][2] - m8), pE3 = __expf(s[kk][3] - m8);
            float pO0 = __expf(s[kk][4] - m0), pO1 = __expf(s[kk][5] - m0);
            float pO2 = __expf(s[kk][6] - m8), pO3 = __expf(s[kk][7] - m8);
            l0 += pE0 + pE1 + pO0 + pO1;
            l8 += pE2 + pE3 + pO2 + pO3;
            pa[kk][0] = pack2(pE0, pE1);
            pa[kk][1] = pack2(pE2, pE3);
            pa[kk][2] = pack2(pO0, pO1);
            pa[kk][3] = pack2(pO2, pO3);
        }
    }

    // ---- final PV for tile 31 (buffer 31&3 not overwritten after loop) ----
    {
        const __half* Vlast = smh + (31 & 3) * AT_BUFH + AT_VOFH;
#pragma unroll
        for (int kk = 0; kk < 4; kk++)
#pragma unroll
            for (int vt = 0; vt < 8; vt++) {
                int vrow = (8 * vt + g) * VS_STRH;
                uint32_t b0 = *(const uint32_t*)&Vlast[vrow + 16 * kk + 2 * qq];
                uint32_t b1 = *(const uint32_t*)&Vlast[vrow + 16 * kk + 8 + 2 * qq];
                mma_f16(oAcc[vt], pa[kk], b0, b1);
            }
    }

    // reduce l across the quad (lanes share rows)
    l0 += __shfl_xor_sync(0xffffffffu, l0, 1);
    l0 += __shfl_xor_sync(0xffffffffu, l0, 2);
    l8 += __shfl_xor_sync(0xffffffffu, l8, 1);
    l8 += __shfl_xor_sync(0xffffffffu, l8, 2);

    const float inv = 0.04419417382415922f;   // 1/sqrt(512)
    float sc0 = inv / l0, sc8 = inv / l8;

    float* op0 = out + ((size_t)b * N_ + qrow) * E_ + h * 64;
    float* op8 = out + ((size_t)b * N_ + qrow + 8) * E_ + h * 64;
#pragma unroll
    for (int vt = 0; vt < 8; vt++) {
        *(float2*)&op0[8 * vt + 2 * qq] = make_float2(oAcc[vt][0] * sc0, oAcc[vt][1] * sc0);
        *(float2*)&op8[8 * vt + 2 * qq] = make_float2(oAcc[vt][2] * sc8, oAcc[vt][3] * sc8);
    }
}

// ---------------- launch ------------------------------------------------------
extern "C" void kernel_launch(void* const* d_in, const int* in_sizes, int n_in,
                              void* d_out, int out_size) {
    const float* x  = (const float*)d_in[0];
    const float* Wk = (const float*)d_in[1];
    const float* bk = (const float*)d_in[2];
    const float* Wv = (const float*)d_in[3];
    const float* bv = (const float*)d_in[4];
    float* out = (float*)d_out;

    __half *xh, *Wkh, *Wvh;
    cudaGetSymbolAddress((void**)&xh,  g_xh);
    cudaGetSymbolAddress((void**)&Wkh, g_Wkh);
    cudaGetSymbolAddress((void**)&Wvh, g_Wvh);

    cudaFuncSetAttribute(proj_mma, cudaFuncAttributeMaxDynamicSharedMemorySize, PJ_SMEM);
    cudaFuncSetAttribute(attn_mma, cudaFuncAttributeMaxDynamicSharedMemorySize, ATTN_SMEM);

    // fp32 -> fp16 with p16 e-permutation (A and B contracted dims match)
    round_perm16<<<(B_ * N_ * E_ / 4 + 255) / 256, 256>>>(x, xh, B_ * N_ * E_ / 4);
    round_perm16<<<(E_ * E_ / 4 + 255) / 256, 256>>>(Wk, Wkh, E_ * E_ / 4);
    round_perm16<<<(E_ * E_ / 4 + 255) / 256, 256>>>(Wv, Wvh, E_ * E_ / 4);

    // K (d p16-permuted) and V (natural) projections
    proj_mma<<<dim3(64, 8, 2), 256, PJ_SMEM>>>(bk, bv);

    // V transpose for PV B-fragments
    vtrans<<<dim3(32, BH_), 256>>>();

    attn_mma<<<dim3(N_ / 128, BH_), 256, ATTN_SMEM>>>(out);
}

// round 17
// speedup vs baseline: 1.1239x; 1.1239x over previous
#include <cuda_runtime.h>
#include <cuda_fp16.h>
#include <math.h>
#include <cstdint>

// Problem constants
#define B_  4
#define N_  2048
#define E_  512
#define H_  8
#define D_  64
#define BH_ 32   // B_*H_

// ---------------- scratch (static __device__; no allocations allowed) -------
// "p16" = within-16-group interleave: pos 4j..4j+3 <- cols (2j,2j+1,2j+8,2j+9)
__device__ __half g_xh [B_ * N_ * E_];    // x, fp16, e p16-permuted
__device__ __half g_Wkh[E_ * E_];         // Wk, fp16, e p16-permuted
__device__ __half g_Wvh[E_ * E_];         // Wv, fp16, e p16-permuted
__device__ __half g_Kh [BH_ * N_ * D_];   // K [bh][n][d p16-permuted] fp16
__device__ __half g_Vh [BH_ * N_ * D_];   // V [bh][n][d] natural fp16
__device__ __half g_VTh[BH_ * D_ * N_];   // V^T [bh][d][n p16-permuted] fp16

// ---------------- helpers (sm_80-era PTX only) --------------------------------
__device__ __forceinline__ void mma_f16(float* d, const uint32_t* a,
                                        uint32_t b0, uint32_t b1) {
    asm volatile(
        "mma.sync.aligned.m16n8k16.row.col.f32.f16.f16.f32 "
        "{%0,%1,%2,%3}, {%4,%5,%6,%7}, {%8,%9}, {%0,%1,%2,%3};\n"
        : "+f"(d[0]), "+f"(d[1]), "+f"(d[2]), "+f"(d[3])
        : "r"(a[0]), "r"(a[1]), "r"(a[2]), "r"(a[3]), "r"(b0), "r"(b1));
}
__device__ __forceinline__ uint32_t pack2(float x, float y) {
    __half2 h = __floats2half2_rn(x, y);
    return *(uint32_t*)&h;
}
__device__ __forceinline__ uint32_t ex2h2(uint32_t a) {    // 2x exp2 in 1 MUFU
    uint32_t r;
    asm("ex2.approx.f16x2 %0, %1;" : "=r"(r) : "r"(a));
    return r;
}
__device__ __forceinline__ float2 h2f2(uint32_t h) {
    __half2 v = *(__half2*)&h;
    return __half22float2(v);
}
__device__ __forceinline__ uint32_t smem_u32(const void* p) {
    uint32_t a;
    asm("{ .reg .u64 t; cvta.to.shared.u64 t, %1; cvt.u32.u64 %0, t; }"
        : "=r"(a) : "l"(p));
    return a;
}
#define CP16(dst, src) \
    asm volatile("cp.async.cg.shared.global [%0], [%1], 16;" :: "r"(dst), "l"(src) : "memory")
#define CP_COMMIT() asm volatile("cp.async.commit_group;" ::: "memory")
#define CP_WAIT(n)  asm volatile("cp.async.wait_group %0;" :: "n"(n) : "memory")

// ---------------- fp32 -> fp16 + p16 permutation ------------------------------
// out[16G + 4j + {0,1,2,3}] = in[16G + {2j, 2j+1, 2j+8, 2j+9}]
__global__ void round_perm16(const float* __restrict__ src,
                             __half* __restrict__ dst, int nq) {
    int i = blockIdx.x * 256 + threadIdx.x;
    if (i >= nq) return;
    int G = i >> 2, j = i & 3;
    int base = 16 * G + 2 * j;
    float2 a = *(const float2*)(src + base);      // cols 2j, 2j+1
    float2 b = *(const float2*)(src + base + 8);  // cols 2j+8, 2j+9
    uint2 o = make_uint2(pack2(a.x, a.y), pack2(b.x, b.y));
    *(uint2*)(dst + 4 * i) = o;
}

// ---------------- K/V projection GEMM (fp16 mma, cp.async 2-stage) -----------
// Tile 128m x 64c, z: 0=K, 1=V. 16 e-chunks of 32 (2 ksteps of k16).
// Stride 80 halfs (== 16 mod 64): paired LDS.64 fragments conflict-free.
#define PJ_STRH 80
#define PJ_WOFH (128 * PJ_STRH)              // 10240 halfs
#define PJ_BUFH (192 * PJ_STRH)              // 15360 halfs per stage
#define PJ_SMEM (2 * PJ_BUFH * 2)            // 61440 B

__device__ __forceinline__ void pj_issue(uint32_t sb, int stage, int k0,
                                         const __half* __restrict__ x,
                                         const __half* __restrict__ W,
                                         int m0, int c0, int tid) {
    uint32_t base = sb + stage * (PJ_BUFH * 2);
#pragma unroll
    for (int it = 0; it < 2; it++) {           // xs: 128 rows x 4 chunks = 512
        int i = it * 256 + tid;
        int r = i >> 2, c8 = (i & 3) * 8;
        CP16(base + (r * PJ_STRH + c8) * 2,
             x + (size_t)(m0 + r) * E_ + k0 + c8);
    }
    {                                          // ws: 64 rows x 4 chunks = 256
        int i = tid;
        int r = i >> 2, c8 = (i & 3) * 8;
        CP16(base + (PJ_WOFH + r * PJ_STRH + c8) * 2,
             W + (size_t)(c0 + r) * E_ + k0 + c8);
    }
    CP_COMMIT();
}

__global__ void __launch_bounds__(256) proj_mma(const float* __restrict__ bk,
                                                const float* __restrict__ bv) {
    extern __shared__ __half smh[];
    uint32_t sb = smem_u32(smh);
    int tid = threadIdx.x;
    int w = tid >> 5, lane = tid & 31;
    int qq = lane & 3, g = lane >> 2;
    int m0 = blockIdx.x * 128;
    int h  = blockIdx.y;
    int c0 = h * 64;
    int z  = blockIdx.z;
    const __half* x    = g_xh;
    const __half* W    = z ? g_Wvh : g_Wkh;
    const float*  bias = z ? bv : bk;
    __half* dst        = z ? g_Vh : g_Kh;

    float acc[8][4];
#pragma unroll
    for (int i = 0; i < 8; i++)
#pragma unroll
        for (int j = 0; j < 4; j++) acc[i][j] = 0.f;

    pj_issue(sb, 0, 0, x, W, m0, c0, tid);

    for (int ec = 0; ec < 16; ec++) {
        if (ec < 15) pj_issue(sb, (ec + 1) & 1, (ec + 1) * 32, x, W, m0, c0, tid);
        if (ec < 15) { CP_WAIT(1); } else { CP_WAIT(0); }
        __syncthreads();

        const __half* bf = smh + (ec & 1) * PJ_BUFH;
        uint32_t af[2][4];
#pragma unroll
        for (int kk = 0; kk < 2; kk++) {       // paired A-frag loads (p16 e-dim)
            uint2 lo = *(const uint2*)&bf[(16 * w + g) * PJ_STRH + 16 * kk + 4 * qq];
            uint2 hi = *(const uint2*)&bf[(16 * w + g + 8) * PJ_STRH + 16 * kk + 4 * qq];
            af[kk][0] = lo.x; af[kk][2] = lo.y;
            af[kk][1] = hi.x; af[kk][3] = hi.y;
        }
#pragma unroll
        for (int nt = 0; nt < 8; nt++) {
#pragma unroll
            for (int kk = 0; kk < 2; kk++) {   // paired B-frag loads
                uint2 bb = *(const uint2*)&bf[PJ_WOFH + (8 * nt + g) * PJ_STRH + 16 * kk + 4 * qq];
                mma_f16(acc[nt], af[kk], bb.x, bb.y);
            }
        }
        __syncthreads();
    }

    // epilogue: bias add in fp32 (original col index), pack fp16
    int r0 = m0 + 16 * w + g;
    int b0i = r0 >> 11, n0i = r0 & 2047;
    int bh = b0i * 8 + h;
    __half* p0 = dst + ((size_t)bh * N_ + n0i) * D_;
    __half* p8 = p0 + 8 * D_;
#pragma unroll
    for (int nt = 0; nt < 8; nt++) {
        int c = 8 * nt + 2 * qq;               // original output col (local)
        float bb0 = bias[c0 + c], bb1 = bias[c0 + c + 1];
        // K gets d p16-permuted on store; V stays natural
        int cb = z ? c : (16 * (nt >> 1) + 4 * qq + 2 * (nt & 1));
        *(uint32_t*)&p0[cb] = pack2(acc[nt][0] + bb0, acc[nt][1] + bb1);
        *(uint32_t*)&p8[cb] = pack2(acc[nt][2] + bb0, acc[nt][3] + bb1);
    }
}

// ---------------- V transpose: [bh][n][d] -> [bh][d][n p16-permuted] ---------
// Key (n) permutation within 16-groups makes PV B-fragments paired LDS.64.
__global__ void __launch_bounds__(256) vtrans() {
    __shared__ __half t[64][65];
    int bh = blockIdx.y;
    int n0 = blockIdx.x * 64;
    int tid = threadIdx.x;
    const __half* src = g_Vh + ((size_t)bh * N_ + n0) * D_;
#pragma unroll
    for (int it = 0; it < 16; it++) {
        int i = it * 256 + tid;
        int r = i >> 6, c = i & 63;
        t[r][c] = src[(size_t)r * D_ + c];
    }
    __syncthreads();
    __half* dstb = g_VTh + (size_t)bh * D_ * N_ + n0;
#pragma unroll
    for (int it = 0; it < 16; it++) {
        int i = it * 256 + tid;
        int d = i >> 6, n = i & 63;
        // forward p16 map: col j (within 16) -> position
        int j = n & 15;
        int pos = (j < 8) ? (4 * (j >> 1) + (j & 1))
                          : (4 * ((j & 7) >> 1) + 2 + (j & 1));
        int np = (n & ~15) + pos;
        dstb[(size_t)d * N_ + np] = t[n][d];
    }
}

// ---------------- fp16 mma flash attention -----------------------------------
// 4-buffer cp.async ring, ONE barrier/iter, deferred PV (ring-4 proven R15).
// log2-domain scores (Q pre-scaled by log2e) -> softmax via ex2.approx.f16x2:
// 16 MUFU/iter (was 32), ex2 output IS the packed P A-frag. PV B-frags paired
// (V^T key-p16-permuted, stride 80 == 16 mod 64, conflict-free).
#define KS_STRH 80
#define VS_STRH 80
#define AT_VOFH (64 * KS_STRH)                // 5120 halfs
#define AT_BUFH (64 * KS_STRH + 64 * VS_STRH) // 10240 halfs per stage
#define ATTN_SMEM (4 * AT_BUFH * 2)           // 81920 B

__device__ __forceinline__ void at_issue(uint32_t sb, int stage, int k0,
                                         const __half* __restrict__ Kb,
                                         const __half* __restrict__ VTb, int tid) {
    uint32_t base = sb + stage * (AT_BUFH * 2);
#pragma unroll
    for (int it = 0; it < 2; it++) {          // K tile: 64 keys x 8 chunks = 512
        int i = it * 256 + tid;
        int r = i >> 3, c8 = (i & 7) * 8;
        CP16(base + (r * KS_STRH + c8) * 2,
             Kb + (size_t)(k0 + r) * D_ + c8);
    }
#pragma unroll
    for (int it = 0; it < 2; it++) {          // V^T tile: 64 d x 8 chunks = 512
        int i = it * 256 + tid;
        int r = i >> 3, c8 = (i & 7) * 8;
        CP16(base + (AT_VOFH + r * VS_STRH + c8) * 2,
             VTb + (size_t)r * N_ + k0 + c8);
    }
    CP_COMMIT();
}

__global__ void __launch_bounds__(256, 2) attn_mma(float* __restrict__ out) {
    extern __shared__ __half smh[];
    uint32_t sb = smem_u32(smh);

    int tid = threadIdx.x;
    int w = tid >> 5, lane = tid & 31;
    int qq = lane & 3, g = lane >> 2;
    int q0 = blockIdx.x * 128;
    int bh = blockIdx.y;
    int b = bh >> 3, h = bh & 7;

    const __half* Kb  = g_Kh  + (size_t)bh * N_ * D_;
    const __half* VTb = g_VTh + (size_t)bh * D_ * N_;

    // Q fragments: paired uint2 gmem loads, then scale by log2e (log2 domain)
    int qrow = q0 + 16 * w + g;
    uint32_t qf[4][4];
    {
        __half2 l2e = __floats2half2_rn(1.4426950408889634f, 1.4426950408889634f);
#pragma unroll
        for (int dk = 0; dk < 4; dk++) {
            uint2 lo = *(const uint2*)&Kb[(size_t)qrow * D_ + 16 * dk + 4 * qq];
            uint2 hi = *(const uint2*)&Kb[(size_t)(qrow + 8) * D_ + 16 * dk + 4 * qq];
            qf[dk][0] = lo.x; qf[dk][2] = lo.y;
            qf[dk][1] = hi.x; qf[dk][3] = hi.y;
#pragma unroll
            for (int j = 0; j < 4; j++) {
                __half2 v = __hmul2(*(__half2*)&qf[dk][j], l2e);
                qf[dk][j] = *(uint32_t*)&v;
            }
        }
    }

    float oAcc[8][4];
#pragma unroll
    for (int i = 0; i < 8; i++)
#pragma unroll
        for (int j = 0; j < 4; j++) oAcc[i][j] = 0.f;
    float m0 = -1e30f, m8 = -1e30f, l0 = 0.f, l8 = 0.f;
    uint32_t pa[4][4];                         // deferred P fragments (tile t-1)

    at_issue(sb, 0, 0, Kb, VTb, tid);

    for (int t = 0; t < 32; t++) {
        if (t < 31) at_issue(sb, (t + 1) & 3, (t + 1) * 64, Kb, VTb, tid);
        if (t < 31) { CP_WAIT(1); } else { CP_WAIT(0); }
        __syncthreads();

        const __half* Ksb = smh + (t & 3) * AT_BUFH;

        // ---- S(t) in log2 domain: all 64 keys, paired B-frag loads ----
        float s[4][8];
#pragma unroll
        for (int kk = 0; kk < 4; kk++) {
#pragma unroll
            for (int j = 0; j < 8; j++) s[kk][j] = 0.f;
            int rowE = (16 * kk + g) * KS_STRH;
            int rowO = (16 * kk + 8 + g) * KS_STRH;
#pragma unroll
            for (int dk = 0; dk < 4; dk++) {
                uint2 eb = *(const uint2*)&Ksb[rowE + 16 * dk + 4 * qq];
                mma_f16(&s[kk][0], qf[dk], eb.x, eb.y);
                uint2 ob = *(const uint2*)&Ksb[rowO + 16 * dk + 4 * qq];
                mma_f16(&s[kk][4], qf[dk], ob.x, ob.y);
            }
        }

        // ---- PV(t-1): paired B loads (key-p16 V^T); overlaps softmax(t) ----
        if (t > 0) {
            const __half* Vprev = smh + ((t + 3) & 3) * AT_BUFH + AT_VOFH;
#pragma unroll
            for (int kk = 0; kk < 4; kk++)
#pragma unroll
                for (int vt = 0; vt < 8; vt++) {
                    uint2 bv = *(const uint2*)&Vprev[(8 * vt + g) * VS_STRH + 16 * kk + 4 * qq];
                    mma_f16(oAcc[vt], pa[kk], bv.x, bv.y);
                }
        }

        // ---- online max (exact, log2 domain) ----
        float r0 = s[0][0], r8 = s[0][2];
#pragma unroll
        for (int kk = 0; kk < 4; kk++) {
            r0 = fmaxf(r0, fmaxf(fmaxf(s[kk][0], s[kk][1]), fmaxf(s[kk][4], s[kk][5])));
            r8 = fmaxf(r8, fmaxf(fmaxf(s[kk][2], s[kk][3]), fmaxf(s[kk][6], s[kk][7])));
        }
        r0 = fmaxf(r0, __shfl_xor_sync(0xffffffffu, r0, 1));
        r0 = fmaxf(r0, __shfl_xor_sync(0xffffffffu, r0, 2));
        r8 = fmaxf(r8, __shfl_xor_sync(0xffffffffu, r8, 1));
        r8 = fmaxf(r8, __shfl_xor_sync(0xffffffffu, r8, 2));
        float m0n = fmaxf(m0, r0), m8n = fmaxf(m8, r8);
        float al0 = exp2f(m0 - m0n), al8 = exp2f(m8 - m8n);
        m0 = m0n; m8 = m8n;
        l0 *= al0; l8 *= al8;
        if (al0 != 1.f || al8 != 1.f) {        // rescale only when max moved
#pragma unroll
            for (int vt = 0; vt < 8; vt++) {
                oAcc[vt][0] *= al0; oAcc[vt][1] *= al0;
                oAcc[vt][2] *= al8; oAcc[vt][3] *= al8;
            }
        }

        // ---- p = ex2(s - m) on half2 pairs; output IS the P A-frag ----
#pragma unroll
        for (int kk = 0; kk < 4; kk++) {
            uint32_t pE01 = ex2h2(pack2(s[kk][0] - m0, s[kk][1] - m0));
            uint32_t pE23 = ex2h2(pack2(s[kk][2] - m8, s[kk][3] - m8));
            uint32_t pO01 = ex2h2(pack2(s[kk][4] - m0, s[kk][5] - m0));
            uint32_t pO23 = ex2h2(pack2(s[kk][6] - m8, s[kk][7] - m8));
            float2 fE01 = h2f2(pE01), fE23 = h2f2(pE23);
            float2 fO01 = h2f2(pO01), fO23 = h2f2(pO23);
            l0 += fE01.x + fE01.y + fO01.x + fO01.y;
            l8 += fE23.x + fE23.y + fO23.x + fO23.y;
            pa[kk][0] = pE01;
            pa[kk][1] = pE23;
            pa[kk][2] = pO01;
            pa[kk][3] = pO23;
        }
    }

    // ---- final PV for tile 31 (buffer 31&3 not overwritten after loop) ----
    {
        const __half* Vlast = smh + (31 & 3) * AT_BUFH + AT_VOFH;
#pragma unroll
        for (int kk = 0; kk < 4; kk++)
#pragma unroll
            for (int vt = 0; vt < 8; vt++) {
                uint2 bv = *(const uint2*)&Vlast[(8 * vt + g) * VS_STRH + 16 * kk + 4 * qq];
                mma_f16(oAcc[vt], pa[kk], bv.x, bv.y);
            }
    }

    // reduce l across the quad (lanes share rows)
    l0 += __shfl_xor_sync(0xffffffffu, l0, 1);
    l0 += __shfl_xor_sync(0xffffffffu, l0, 2);
    l8 += __shfl_xor_sync(0xffffffffu, l8, 1);
    l8 += __shfl_xor_sync(0xffffffffu, l8, 2);

    const float inv = 0.04419417382415922f;   // 1/sqrt(512)
    float sc0 = inv / l0, sc8 = inv / l8;

    float* op0 = out + ((size_t)b * N_ + qrow) * E_ + h * 64;
    float* op8 = out + ((size_t)b * N_ + qrow + 8) * E_ + h * 64;
#pragma unroll
    for (int vt = 0; vt < 8; vt++) {
        *(float2*)&op0[8 * vt + 2 * qq] = make_float2(oAcc[vt][0] * sc0, oAcc[vt][1] * sc0);
        *(float2*)&op8[8 * vt + 2 * qq] = make_float2(oAcc[vt][2] * sc8, oAcc[vt][3] * sc8);
    }
}

// ---------------- launch ------------------------------------------------------
extern "C" void kernel_launch(void* const* d_in, const int* in_sizes, int n_in,
                              void* d_out, int out_size) {
    const float* x  = (const float*)d_in[0];
    const float* Wk = (const float*)d_in[1];
    const float* bk = (const float*)d_in[2];
    const float* Wv = (const float*)d_in[3];
    const float* bv = (const float*)d_in[4];
    float* out = (float*)d_out;

    __half *xh, *Wkh, *Wvh;
    cudaGetSymbolAddress((void**)&xh,  g_xh);
    cudaGetSymbolAddress((void**)&Wkh, g_Wkh);
    cudaGetSymbolAddress((void**)&Wvh, g_Wvh);

    cudaFuncSetAttribute(proj_mma, cudaFuncAttributeMaxDynamicSharedMemorySize, PJ_SMEM);
    cudaFuncSetAttribute(attn_mma, cudaFuncAttributeMaxDynamicSharedMemorySize, ATTN_SMEM);

    // fp32 -> fp16 with p16 e-permutation (A and B contracted dims match)
    round_perm16<<<(B_ * N_ * E_ / 4 + 255) / 256, 256>>>(x, xh, B_ * N_ * E_ / 4);
    round_perm16<<<(E_ * E_ / 4 + 255) / 256, 256>>>(Wk, Wkh, E_ * E_ / 4);
    round_perm16<<<(E_ * E_ / 4 + 255) / 256, 256>>>(Wv, Wvh, E_ * E_ / 4);

    // K (d p16-permuted) and V (natural) projections
    proj_mma<<<dim3(64, 8, 2), 256, PJ_SMEM>>>(bk, bv);

    // V transpose with key-p16 permutation (pairs the PV B-fragments)
    vtrans<<<dim3(32, BH_), 256>>>();

    attn_mma<<<dim3(N_ / 128, BH_), 256, ATTN_SMEM>>>(out);
}